// round 7
// baseline (speedup 1.0000x reference)
#include <cuda_runtime.h>
#include <cuda_bf16.h>
#include <cstdint>

#define NUM_HEADS 12
#define HEAD_DIM  64
#define SEQ       2048
#define BATCH     2
#define EMB       768
#define SEG       256
#define KDIM      768

// Scratch — EXACT R4 set (proven to pass the allocation guard)
__device__ float g_q[BATCH*NUM_HEADS*SEQ*HEAD_DIM];
__device__ float g_k[BATCH*NUM_HEADS*SEQ*HEAD_DIM];
__device__ float g_v[BATCH*NUM_HEADS*SEQ*HEAD_DIM];
__device__ float g_ctx[BATCH*SEQ*EMB];

// ===========================================================================
// Warp-level MMA helpers (compute_100-safe: sm_80-era PTX)
// ===========================================================================
__device__ __forceinline__ uint32_t smem_u32(const void* p) {
  uint32_t a;
  asm("{ .reg .u64 t; cvta.to.shared.u64 t, %1; cvt.u32.u64 %0, t; }" : "=r"(a) : "l"(p));
  return a;
}
__device__ __forceinline__ void ldsm4(uint32_t* r, uint32_t addr) {
  asm volatile("ldmatrix.sync.aligned.m8n8.x4.shared.b16 {%0,%1,%2,%3}, [%4];"
               : "=r"(r[0]), "=r"(r[1]), "=r"(r[2]), "=r"(r[3]) : "r"(addr));
}
__device__ __forceinline__ void mma_bf16(float* d, const uint32_t* a,
                                         uint32_t b0, uint32_t b1) {
  asm volatile(
      "mma.sync.aligned.m16n8k16.row.col.f32.bf16.bf16.f32 "
      "{%0,%1,%2,%3}, {%4,%5,%6,%7}, {%8,%9}, {%0,%1,%2,%3};"
      : "+f"(d[0]), "+f"(d[1]), "+f"(d[2]), "+f"(d[3])
      : "r"(a[0]), "r"(a[1]), "r"(a[2]), "r"(a[3]), "r"(b0), "r"(b1));
}

#define SWZ(off) ((off) ^ (((off) >> 3) & 0x70))

__device__ __forceinline__ uint32_t pack2(float a, float b) {
  __nv_bfloat162 p = __halves2bfloat162(__float2bfloat16(a), __float2bfloat16(b));
  return *reinterpret_cast<uint32_t*>(&p);
}

// ===========================================================================
// GEMM: C[m][n] = sum_k A[m][k] * W[n][k] + bias[n]
// Split-precision bf16 (hi*hi + hi*lo + lo*hi), fp32 register accumulators.
// CTA tile 128x128, K chunked by 64. 512 threads, warp grid 4(M) x 4(N),
// warp tile 32x32 (2 m-atoms x 4 n-atoms of m16n8k16). Staging: threads
// 0-255 stage A, 256-511 stage W (one half-row of one operand each).
// mode 0: QKV (blockIdx.z selects q/k/v, scatter to (B,H,S,D))
// mode 1: out projection (row-major to dout)
// ===========================================================================
#define GK      64
#define NCHUNK  (KDIM / GK)            // 12
#define SA_HI   0
#define SA_LO   16384
#define SB_HI   32768
#define SB_LO   49152
#define GEMM_SMEM 65536

__global__ __launch_bounds__(512) void gemm_hmma_kernel(
    const float* __restrict__ A0,
    const float* __restrict__ W0, const float* __restrict__ b0,
    const float* __restrict__ W1, const float* __restrict__ b1,
    const float* __restrict__ W2, const float* __restrict__ b2,
    float* __restrict__ dout, int mode) {
  extern __shared__ char sm[];
  const uint32_t sbase = smem_u32(sm);
  const int tid  = threadIdx.x;
  const int wid  = tid >> 5;
  const int lane = tid & 31;
  const int m0 = blockIdx.y * 128;
  const int n0 = blockIdx.x * 128;
  const int z  = blockIdx.z;

  const float* A    = (mode == 1) ? g_ctx : A0;
  const float* W    = (z == 0) ? W0 : (z == 1) ? W1 : W2;
  const float* bias = (z == 0) ? b0 : (z == 1) ? b1 : b2;
  float* outp = (mode == 1) ? dout : ((z == 0) ? g_q : (z == 1) ? g_k : g_v);

  // staging: thread covers one half-row of A (tid<256) or W (tid>=256)
  const int sid = tid & 255;
  const int r   = sid >> 1;           // 0..127
  const int cb  = (sid & 1) * 32;     // 0 or 32
  const bool isA = (tid < 256);
  const float* src = isA ? (A + (size_t)(m0 + r) * KDIM + cb)
                         : (W + (size_t)(n0 + r) * KDIM + cb);
  const int dhi = isA ? SA_HI : SB_HI;
  const int dlo = isA ? SA_LO : SB_LO;

  // warp tile position (4x4 grid of 32x32 tiles)
  const int mw = (wid >> 2) * 32;
  const int nw = (wid & 3) * 32;

  // ldmatrix lane addressing
  const int lrow = lane & 15;
  const int lkb  = (lane >> 4) * 16;  // 8 bf16 = 16B

  float acc[8][4];                    // [mi*4+ni][4]
#pragma unroll
  for (int i = 0; i < 8; i++)
#pragma unroll
    for (int j = 0; j < 4; j++) acc[i][j] = 0.f;

  for (int c = 0; c < NCHUNK; c++) {
    // ---- stage: fp32 -> bf16 hi/lo, swizzled K-major (64 bf16/row) ----
#pragma unroll
    for (int u = 0; u < 8; u++) {
      float4 v = *(const float4*)(src + c * GK + u * 4);
      const uint32_t sw = SWZ((uint32_t)(r * 128 + (cb + u * 4) * 2));
      float hx = __bfloat162float(__float2bfloat16(v.x));
      float hy = __bfloat162float(__float2bfloat16(v.y));
      float hz = __bfloat162float(__float2bfloat16(v.z));
      float hw = __bfloat162float(__float2bfloat16(v.w));
      *(uint2*)(sm + dhi + sw) = make_uint2(pack2(hx, hy), pack2(hz, hw));
      *(uint2*)(sm + dlo + sw) =
          make_uint2(pack2(v.x - hx, v.y - hy), pack2(v.z - hz, v.w - hw));
    }
    __syncthreads();

    // ---- compute: 4 K16 steps, 24 mma each ----
#pragma unroll
    for (int ks = 0; ks < 4; ks++) {
      const uint32_t koff = (uint32_t)(ks * 32 + lkb);
      uint32_t ah[2][4], al[2][4];
#pragma unroll
      for (int mi = 0; mi < 2; mi++) {
        const uint32_t off = (uint32_t)((mw + mi * 16 + lrow) * 128) + koff;
        ldsm4(ah[mi], sbase + SA_HI + SWZ(off));
        ldsm4(al[mi], sbase + SA_LO + SWZ(off));
      }
      uint32_t bh[2][4], bl[2][4];
#pragma unroll
      for (int nb = 0; nb < 2; nb++) {
        const uint32_t off = (uint32_t)((nw + nb * 16 + lrow) * 128) + koff;
        ldsm4(bh[nb], sbase + SB_HI + SWZ(off));
        ldsm4(bl[nb], sbase + SB_LO + SWZ(off));
      }
#pragma unroll
      for (int ni = 0; ni < 4; ni++) {
        const int nb = ni >> 1, sel = ni & 1;
        const uint32_t bh0 = bh[nb][sel], bh1 = bh[nb][2 + sel];
        const uint32_t bl0 = bl[nb][sel], bl1 = bl[nb][2 + sel];
#pragma unroll
        for (int mi = 0; mi < 2; mi++) {
          mma_bf16(acc[mi * 4 + ni], ah[mi], bh0, bh1);  // hi*hi
          mma_bf16(acc[mi * 4 + ni], ah[mi], bl0, bl1);  // hi*lo
          mma_bf16(acc[mi * 4 + ni], al[mi], bh0, bh1);  // lo*hi
        }
      }
    }
    __syncthreads();
  }

  // ---- epilogue: bias add + store ----
  const int er = lane >> 2;        // 0..7
  const int ec = (lane & 3) * 2;   // 0,2,4,6
#pragma unroll
  for (int mi = 0; mi < 2; mi++) {
#pragma unroll
    for (int rr = 0; rr < 2; rr++) {
      const int m = m0 + mw + mi * 16 + rr * 8 + er;
      if (mode == 1) {
        float* orow = outp + (size_t)m * EMB;
#pragma unroll
        for (int ni = 0; ni < 4; ni++) {
          const int n = n0 + nw + ni * 8 + ec;
          float2 v;
          v.x = acc[mi * 4 + ni][rr * 2 + 0] + bias[n];
          v.y = acc[mi * 4 + ni][rr * 2 + 1] + bias[n + 1];
          *(float2*)(orow + n) = v;
        }
      } else {
        const int b = m >> 11;
        const int s = m & 2047;
#pragma unroll
        for (int ni = 0; ni < 4; ni++) {
          const int n = n0 + nw + ni * 8 + ec;
          const int h = n >> 6;
          const int d = n & 63;
          float2 v;
          v.x = acc[mi * 4 + ni][rr * 2 + 0] + bias[n];
          v.y = acc[mi * 4 + ni][rr * 2 + 1] + bias[n + 1];
          *(float2*)(outp + (((size_t)b * NUM_HEADS + h) * SEQ + s) * HEAD_DIM + d) = v;
        }
      }
    }
  }
}

// ===========================================================================
// Segment-local attention (R1-proven). DILATION=1 => block-diagonal.
// One CTA per (b, h, seg, qtile of 64 rows): grid 768, block 256.
// ===========================================================================
#define SMEM_FLOATS (64*68 + 64*256 + 256*68 + 256*68 + 64)
#define SMEM_BYTES  (SMEM_FLOATS * 4)

__global__ __launch_bounds__(256) void attn_kernel() {
  extern __shared__ float smf[];
  float* Qt   = smf;
  float* Kt   = Qt + 64*68;
  float* Vs   = Kt + 64*256;
  float* Pt   = Vs + 256*68;
  float* rinv = Pt + 256*68;

  const int tid = threadIdx.x;
  int bx = blockIdx.x;
  const int qt  = bx & 3;   bx >>= 2;
  const int seg = bx & 7;   bx >>= 3;
  const int hh  = bx % NUM_HEADS;
  const int bb  = bx / NUM_HEADS;

  const size_t head_off = (((size_t)bb*NUM_HEADS + hh)*SEQ + seg*SEG) * HEAD_DIM;
  const float* qbase = g_q + head_off + (size_t)qt*64*HEAD_DIM;
  const float* kbase = g_k + head_off;
  const float* vbase = g_v + head_off;

  {
    const int j = tid;
#pragma unroll
    for (int u = 0; u < 16; u++) {
      float4 kv = *(const float4*)(kbase + j*64 + u*4);
      Kt[(u*4+0)*256 + j] = kv.x;
      Kt[(u*4+1)*256 + j] = kv.y;
      Kt[(u*4+2)*256 + j] = kv.z;
      Kt[(u*4+3)*256 + j] = kv.w;
      float4 vv = *(const float4*)(vbase + j*64 + u*4);
      *(float4*)(Vs + j*68 + u*4) = vv;
    }
  }
  {
    const int r  = tid & 63;
    const int qu = tid >> 6;
#pragma unroll
    for (int u = 0; u < 4; u++) {
      const int d0 = qu*16 + u*4;
      float4 qv = *(const float4*)(qbase + r*64 + d0);
      Qt[(d0+0)*68 + r] = qv.x * 0.125f;
      Qt[(d0+1)*68 + r] = qv.y * 0.125f;
      Qt[(d0+2)*68 + r] = qv.z * 0.125f;
      Qt[(d0+3)*68 + r] = qv.w * 0.125f;
    }
  }
  __syncthreads();

  {
    const int tj = tid & 31;
    const int tr = tid >> 5;
    float acc[8][8];
#pragma unroll
    for (int u = 0; u < 8; u++)
#pragma unroll
      for (int ri = 0; ri < 8; ri++) acc[u][ri] = 0.f;

    for (int d = 0; d < 64; d++) {
      float qf[8];
      *(float4*)(qf)     = *(const float4*)(Qt + d*68 + tr*8);
      *(float4*)(qf + 4) = *(const float4*)(Qt + d*68 + tr*8 + 4);
#pragma unroll
      for (int u = 0; u < 8; u++) {
        const float kf = Kt[d*256 + tj + 32*u];
#pragma unroll
        for (int ri = 0; ri < 8; ri++) acc[u][ri] += kf * qf[ri];
      }
    }
#pragma unroll
    for (int u = 0; u < 8; u++) {
      const int j = tj + 32*u;
      *(float4*)(Pt + j*68 + tr*8)     = make_float4(acc[u][0], acc[u][1], acc[u][2], acc[u][3]);
      *(float4*)(Pt + j*68 + tr*8 + 4) = make_float4(acc[u][4], acc[u][5], acc[u][6], acc[u][7]);
    }
  }
  __syncthreads();

  {
    const int r = tid >> 2;
    const int c = tid & 3;
    float mx = -1e30f;
    for (int jj = 0; jj < 64; jj++)
      mx = fmaxf(mx, Pt[(c*64 + jj)*68 + r]);
    mx = fmaxf(mx, __shfl_xor_sync(0xffffffffu, mx, 1));
    mx = fmaxf(mx, __shfl_xor_sync(0xffffffffu, mx, 2));
    float ssum = 0.f;
    for (int jj = 0; jj < 64; jj++) {
      const int idx = (c*64 + jj)*68 + r;
      const float e = __expf(Pt[idx] - mx);
      Pt[idx] = e;
      ssum += e;
    }
    ssum += __shfl_xor_sync(0xffffffffu, ssum, 1);
    ssum += __shfl_xor_sync(0xffffffffu, ssum, 2);
    if (c == 0) rinv[r] = 1.0f / ssum;
  }
  __syncthreads();

  {
    const int tc  = tid & 15;
    const int tr2 = tid >> 4;
    float acc[4][4];
#pragma unroll
    for (int i = 0; i < 4; i++)
#pragma unroll
      for (int j = 0; j < 4; j++) acc[i][j] = 0.f;

    for (int j = 0; j < 256; j++) {
      float pf[4], vf[4];
      *(float4*)pf = *(const float4*)(Pt + j*68 + tr2*4);
      *(float4*)vf = *(const float4*)(Vs + j*68 + tc*4);
#pragma unroll
      for (int i = 0; i < 4; i++)
#pragma unroll
        for (int jj = 0; jj < 4; jj++) acc[i][jj] += pf[i] * vf[jj];
    }

    float* ctxbase = g_ctx + ((size_t)bb*SEQ + seg*SEG + qt*64)*EMB + hh*64;
#pragma unroll
    for (int i = 0; i < 4; i++) {
      const int row  = tr2*4 + i;
      const float iv = rinv[row];
      float4 o = make_float4(acc[i][0]*iv, acc[i][1]*iv, acc[i][2]*iv, acc[i][3]*iv);
      *(float4*)(ctxbase + (size_t)row*EMB + tc*4) = o;
    }
  }
}

// ===========================================================================
extern "C" void kernel_launch(void* const* d_in, const int* in_sizes, int n_in,
                              void* d_out, int out_size) {
  const float* x  = (const float*)d_in[0];
  const float* Wq = (const float*)d_in[1];
  const float* bq = (const float*)d_in[2];
  const float* Wk = (const float*)d_in[3];
  const float* bk = (const float*)d_in[4];
  const float* Wv = (const float*)d_in[5];
  const float* bv = (const float*)d_in[6];
  const float* Wo = (const float*)d_in[7];
  const float* bo = (const float*)d_in[8];
  float* out = (float*)d_out;

  cudaFuncSetAttribute(gemm_hmma_kernel,
                       cudaFuncAttributeMaxDynamicSharedMemorySize, GEMM_SMEM);
  cudaFuncSetAttribute(attn_kernel,
                       cudaFuncAttributeMaxDynamicSharedMemorySize, SMEM_BYTES);

  dim3 gqkv(6, 32, 3);
  gemm_hmma_kernel<<<gqkv, 512, GEMM_SMEM>>>(x, Wq, bq, Wk, bk, Wv, bv,
                                             nullptr, 0);

  attn_kernel<<<768, 256, SMEM_BYTES>>>();

  dim3 gout(6, 32, 1);
  gemm_hmma_kernel<<<gout, 512, GEMM_SMEM>>>(nullptr, Wo, bo, Wo, bo, Wo, bo,
                                             out, 1);
}

// round 8
// speedup vs baseline: 1.2060x; 1.2060x over previous
#include <cuda_runtime.h>
#include <cuda_bf16.h>
#include <cstdint>

#define NUM_HEADS 12
#define HEAD_DIM  64
#define SEQ       2048
#define BATCH     2
#define EMB       768
#define SEG       256
#define KDIM      768

// Scratch — EXACT R4 set (proven to pass the allocation guard)
__device__ float g_q[BATCH*NUM_HEADS*SEQ*HEAD_DIM];
__device__ float g_k[BATCH*NUM_HEADS*SEQ*HEAD_DIM];
__device__ float g_v[BATCH*NUM_HEADS*SEQ*HEAD_DIM];
__device__ float g_ctx[BATCH*SEQ*EMB];

// ===========================================================================
// Warp-level MMA helpers (compute_100-safe: sm_80-era PTX)
// ===========================================================================
__device__ __forceinline__ uint32_t smem_u32(const void* p) {
  uint32_t a;
  asm("{ .reg .u64 t; cvta.to.shared.u64 t, %1; cvt.u32.u64 %0, t; }" : "=r"(a) : "l"(p));
  return a;
}
__device__ __forceinline__ void ldsm4(uint32_t* r, uint32_t addr) {
  asm volatile("ldmatrix.sync.aligned.m8n8.x4.shared.b16 {%0,%1,%2,%3}, [%4];"
               : "=r"(r[0]), "=r"(r[1]), "=r"(r[2]), "=r"(r[3]) : "r"(addr));
}
__device__ __forceinline__ void mma_bf16(float* d, const uint32_t* a,
                                         uint32_t b0, uint32_t b1) {
  asm volatile(
      "mma.sync.aligned.m16n8k16.row.col.f32.bf16.bf16.f32 "
      "{%0,%1,%2,%3}, {%4,%5,%6,%7}, {%8,%9}, {%0,%1,%2,%3};"
      : "+f"(d[0]), "+f"(d[1]), "+f"(d[2]), "+f"(d[3])
      : "r"(a[0]), "r"(a[1]), "r"(a[2]), "r"(a[3]), "r"(b0), "r"(b1));
}

#define SWZ(off) ((off) ^ (((off) >> 3) & 0x70))

__device__ __forceinline__ uint32_t pack2(float a, float b) {
  __nv_bfloat162 p = __halves2bfloat162(__float2bfloat16(a), __float2bfloat16(b));
  return *reinterpret_cast<uint32_t*>(&p);
}

// ===========================================================================
// GEMM: C[m][n] = sum_k A[m][k] * W[n][k] + bias[n]
// Split-precision bf16 (hi*hi + hi*lo + lo*hi), fp32 register accumulators.
// CTA tile 128x128, K chunked by 64. 256 threads, warp grid 4(M) x 2(N),
// warp tile 32x64. REGISTER PREFETCH: chunk c+1 LDGs issue before chunk c's
// MMA phase, hiding global-load latency behind tensor work.
// mode 0: QKV (blockIdx.z selects q/k/v, scatter to (B,H,S,D))
// mode 1: out projection (row-major to dout)
// ===========================================================================
#define GK      64
#define NCHUNK  (KDIM / GK)            // 12
#define OFF_AHI 0
#define OFF_ALO 16384
#define OFF_BHI 32768
#define OFF_BLO 49152
#define GEMM_SMEM 65536

__global__ __launch_bounds__(256) void gemm_hmma_kernel(
    const float* __restrict__ A0,
    const float* __restrict__ W0, const float* __restrict__ b0,
    const float* __restrict__ W1, const float* __restrict__ b1,
    const float* __restrict__ W2, const float* __restrict__ b2,
    float* __restrict__ dout, int mode) {
  extern __shared__ char sm[];
  const uint32_t sbase = smem_u32(sm);
  const int tid  = threadIdx.x;
  const int wid  = tid >> 5;
  const int lane = tid & 31;
  const int m0 = blockIdx.y * 128;
  const int n0 = blockIdx.x * 128;
  const int z  = blockIdx.z;

  const float* A    = (mode == 1) ? g_ctx : A0;
  const float* W    = (z == 0) ? W0 : (z == 1) ? W1 : W2;
  const float* bias = (z == 0) ? b0 : (z == 1) ? b1 : b2;
  float* outp = (mode == 1) ? dout : ((z == 0) ? g_q : (z == 1) ? g_k : g_v);

  // staging indices: thread covers tile row r, K half cb
  const int r  = tid >> 1;           // 0..127
  const int cb = (tid & 1) * 32;     // 0 or 32
  const float* Ap = A + (size_t)(m0 + r) * KDIM + cb;
  const float* Wp = W + (size_t)(n0 + r) * KDIM + cb;

  // warp tile position
  const int mw = (wid >> 1) * 32;    // 0,32,64,96
  const int nw = (wid & 1) * 64;     // 0,64

  // ldmatrix lane addressing
  const int lrow = lane & 15;
  const int lkb  = (lane >> 4) * 16; // 8 bf16 = 16B

  float acc[16][4];                  // [mi*8+ni][4]
#pragma unroll
  for (int i = 0; i < 16; i++)
#pragma unroll
    for (int j = 0; j < 4; j++) acc[i][j] = 0.f;

  // ---- prologue: prefetch chunk 0 into registers ----
  float4 pa[8], pw[8];
#pragma unroll
  for (int u = 0; u < 8; u++) {
    pa[u] = *(const float4*)(Ap + u * 4);
    pw[u] = *(const float4*)(Wp + u * 4);
  }

  for (int c = 0; c < NCHUNK; c++) {
    // ---- stage chunk c from registers: fp32 -> bf16 hi/lo, swizzled ----
#pragma unroll
    for (int u = 0; u < 8; u++) {
      const float4 av = pa[u];
      const float4 wv = pw[u];
      const uint32_t sw = SWZ((uint32_t)(r * 128 + (cb + u * 4) * 2));

      float ahx = __bfloat162float(__float2bfloat16(av.x));
      float ahy = __bfloat162float(__float2bfloat16(av.y));
      float ahz = __bfloat162float(__float2bfloat16(av.z));
      float ahw = __bfloat162float(__float2bfloat16(av.w));
      *(uint2*)(sm + OFF_AHI + sw) = make_uint2(pack2(ahx, ahy), pack2(ahz, ahw));
      *(uint2*)(sm + OFF_ALO + sw) =
          make_uint2(pack2(av.x - ahx, av.y - ahy), pack2(av.z - ahz, av.w - ahw));

      float whx = __bfloat162float(__float2bfloat16(wv.x));
      float why = __bfloat162float(__float2bfloat16(wv.y));
      float whz = __bfloat162float(__float2bfloat16(wv.z));
      float whw = __bfloat162float(__float2bfloat16(wv.w));
      *(uint2*)(sm + OFF_BHI + sw) = make_uint2(pack2(whx, why), pack2(whz, whw));
      *(uint2*)(sm + OFF_BLO + sw) =
          make_uint2(pack2(wv.x - whx, wv.y - why), pack2(wv.z - whz, wv.w - whw));
    }
    __syncthreads();

    // ---- prefetch chunk c+1 (LDGs retire behind the MMA phase) ----
    if (c + 1 < NCHUNK) {
#pragma unroll
      for (int u = 0; u < 8; u++) {
        pa[u] = *(const float4*)(Ap + (c + 1) * GK + u * 4);
        pw[u] = *(const float4*)(Wp + (c + 1) * GK + u * 4);
      }
    }

    // ---- compute chunk c: 4 K16 steps, 48 mma each (R4-proven) ----
#pragma unroll
    for (int ks = 0; ks < 4; ks++) {
      const uint32_t koff = (uint32_t)(ks * 32 + lkb);
      uint32_t ah[2][4], al[2][4];
#pragma unroll
      for (int mi = 0; mi < 2; mi++) {
        const uint32_t off = (uint32_t)((mw + mi * 16 + lrow) * 128) + koff;
        ldsm4(ah[mi], sbase + OFF_AHI + SWZ(off));
        ldsm4(al[mi], sbase + OFF_ALO + SWZ(off));
      }
      uint32_t bh[4][4], bl[4][4];
#pragma unroll
      for (int nb = 0; nb < 4; nb++) {
        const uint32_t off = (uint32_t)((nw + nb * 16 + lrow) * 128) + koff;
        ldsm4(bh[nb], sbase + OFF_BHI + SWZ(off));
        ldsm4(bl[nb], sbase + OFF_BLO + SWZ(off));
      }
#pragma unroll
      for (int ni = 0; ni < 8; ni++) {
        const int nb = ni >> 1, sel = ni & 1;
        const uint32_t bh0 = bh[nb][sel], bh1 = bh[nb][2 + sel];
        const uint32_t bl0 = bl[nb][sel], bl1 = bl[nb][2 + sel];
#pragma unroll
        for (int mi = 0; mi < 2; mi++) {
          mma_bf16(acc[mi * 8 + ni], ah[mi], bh0, bh1);  // hi*hi
          mma_bf16(acc[mi * 8 + ni], ah[mi], bl0, bl1);  // hi*lo
          mma_bf16(acc[mi * 8 + ni], al[mi], bh0, bh1);  // lo*hi
        }
      }
    }
    __syncthreads();
  }

  // ---- epilogue: bias add + store ----
  const int er = lane >> 2;        // 0..7
  const int ec = (lane & 3) * 2;   // 0,2,4,6
#pragma unroll
  for (int mi = 0; mi < 2; mi++) {
#pragma unroll
    for (int rr = 0; rr < 2; rr++) {
      const int m = m0 + mw + mi * 16 + rr * 8 + er;
      if (mode == 1) {
        float* orow = outp + (size_t)m * EMB;
#pragma unroll
        for (int ni = 0; ni < 8; ni++) {
          const int n = n0 + nw + ni * 8 + ec;
          float2 v;
          v.x = acc[mi * 8 + ni][rr * 2 + 0] + bias[n];
          v.y = acc[mi * 8 + ni][rr * 2 + 1] + bias[n + 1];
          *(float2*)(orow + n) = v;
        }
      } else {
        const int b = m >> 11;
        const int s = m & 2047;
#pragma unroll
        for (int ni = 0; ni < 8; ni++) {
          const int n = n0 + nw + ni * 8 + ec;
          const int h = n >> 6;
          const int d = n & 63;
          float2 v;
          v.x = acc[mi * 8 + ni][rr * 2 + 0] + bias[n];
          v.y = acc[mi * 8 + ni][rr * 2 + 1] + bias[n + 1];
          *(float2*)(outp + (((size_t)b * NUM_HEADS + h) * SEQ + s) * HEAD_DIM + d) = v;
        }
      }
    }
  }
}

// ===========================================================================
// Segment-local attention (R1-proven). DILATION=1 => block-diagonal.
// One CTA per (b, h, seg, qtile of 64 rows): grid 768, block 256.
// ===========================================================================
#define SMEM_FLOATS (64*68 + 64*256 + 256*68 + 256*68 + 64)
#define SMEM_BYTES  (SMEM_FLOATS * 4)

__global__ __launch_bounds__(256) void attn_kernel() {
  extern __shared__ float smf[];
  float* Qt   = smf;
  float* Kt   = Qt + 64*68;
  float* Vs   = Kt + 64*256;
  float* Pt   = Vs + 256*68;
  float* rinv = Pt + 256*68;

  const int tid = threadIdx.x;
  int bx = blockIdx.x;
  const int qt  = bx & 3;   bx >>= 2;
  const int seg = bx & 7;   bx >>= 3;
  const int hh  = bx % NUM_HEADS;
  const int bb  = bx / NUM_HEADS;

  const size_t head_off = (((size_t)bb*NUM_HEADS + hh)*SEQ + seg*SEG) * HEAD_DIM;
  const float* qbase = g_q + head_off + (size_t)qt*64*HEAD_DIM;
  const float* kbase = g_k + head_off;
  const float* vbase = g_v + head_off;

  {
    const int j = tid;
#pragma unroll
    for (int u = 0; u < 16; u++) {
      float4 kv = *(const float4*)(kbase + j*64 + u*4);
      Kt[(u*4+0)*256 + j] = kv.x;
      Kt[(u*4+1)*256 + j] = kv.y;
      Kt[(u*4+2)*256 + j] = kv.z;
      Kt[(u*4+3)*256 + j] = kv.w;
      float4 vv = *(const float4*)(vbase + j*64 + u*4);
      *(float4*)(Vs + j*68 + u*4) = vv;
    }
  }
  {
    const int r  = tid & 63;
    const int qu = tid >> 6;
#pragma unroll
    for (int u = 0; u < 4; u++) {
      const int d0 = qu*16 + u*4;
      float4 qv = *(const float4*)(qbase + r*64 + d0);
      Qt[(d0+0)*68 + r] = qv.x * 0.125f;
      Qt[(d0+1)*68 + r] = qv.y * 0.125f;
      Qt[(d0+2)*68 + r] = qv.z * 0.125f;
      Qt[(d0+3)*68 + r] = qv.w * 0.125f;
    }
  }
  __syncthreads();

  {
    const int tj = tid & 31;
    const int tr = tid >> 5;
    float acc[8][8];
#pragma unroll
    for (int u = 0; u < 8; u++)
#pragma unroll
      for (int ri = 0; ri < 8; ri++) acc[u][ri] = 0.f;

    for (int d = 0; d < 64; d++) {
      float qf[8];
      *(float4*)(qf)     = *(const float4*)(Qt + d*68 + tr*8);
      *(float4*)(qf + 4) = *(const float4*)(Qt + d*68 + tr*8 + 4);
#pragma unroll
      for (int u = 0; u < 8; u++) {
        const float kf = Kt[d*256 + tj + 32*u];
#pragma unroll
        for (int ri = 0; ri < 8; ri++) acc[u][ri] += kf * qf[ri];
      }
    }
#pragma unroll
    for (int u = 0; u < 8; u++) {
      const int j = tj + 32*u;
      *(float4*)(Pt + j*68 + tr*8)     = make_float4(acc[u][0], acc[u][1], acc[u][2], acc[u][3]);
      *(float4*)(Pt + j*68 + tr*8 + 4) = make_float4(acc[u][4], acc[u][5], acc[u][6], acc[u][7]);
    }
  }
  __syncthreads();

  {
    const int r = tid >> 2;
    const int c = tid & 3;
    float mx = -1e30f;
    for (int jj = 0; jj < 64; jj++)
      mx = fmaxf(mx, Pt[(c*64 + jj)*68 + r]);
    mx = fmaxf(mx, __shfl_xor_sync(0xffffffffu, mx, 1));
    mx = fmaxf(mx, __shfl_xor_sync(0xffffffffu, mx, 2));
    float ssum = 0.f;
    for (int jj = 0; jj < 64; jj++) {
      const int idx = (c*64 + jj)*68 + r;
      const float e = __expf(Pt[idx] - mx);
      Pt[idx] = e;
      ssum += e;
    }
    ssum += __shfl_xor_sync(0xffffffffu, ssum, 1);
    ssum += __shfl_xor_sync(0xffffffffu, ssum, 2);
    if (c == 0) rinv[r] = 1.0f / ssum;
  }
  __syncthreads();

  {
    const int tc  = tid & 15;
    const int tr2 = tid >> 4;
    float acc[4][4];
#pragma unroll
    for (int i = 0; i < 4; i++)
#pragma unroll
      for (int j = 0; j < 4; j++) acc[i][j] = 0.f;

    for (int j = 0; j < 256; j++) {
      float pf[4], vf[4];
      *(float4*)pf = *(const float4*)(Pt + j*68 + tr2*4);
      *(float4*)vf = *(const float4*)(Vs + j*68 + tc*4);
#pragma unroll
      for (int i = 0; i < 4; i++)
#pragma unroll
        for (int jj = 0; jj < 4; jj++) acc[i][jj] += pf[i] * vf[jj];
    }

    float* ctxbase = g_ctx + ((size_t)bb*SEQ + seg*SEG + qt*64)*EMB + hh*64;
#pragma unroll
    for (int i = 0; i < 4; i++) {
      const int row  = tr2*4 + i;
      const float iv = rinv[row];
      float4 o = make_float4(acc[i][0]*iv, acc[i][1]*iv, acc[i][2]*iv, acc[i][3]*iv);
      *(float4*)(ctxbase + (size_t)row*EMB + tc*4) = o;
    }
  }
}

// ===========================================================================
extern "C" void kernel_launch(void* const* d_in, const int* in_sizes, int n_in,
                              void* d_out, int out_size) {
  const float* x  = (const float*)d_in[0];
  const float* Wq = (const float*)d_in[1];
  const float* bq = (const float*)d_in[2];
  const float* Wk = (const float*)d_in[3];
  const float* bk = (const float*)d_in[4];
  const float* Wv = (const float*)d_in[5];
  const float* bv = (const float*)d_in[6];
  const float* Wo = (const float*)d_in[7];
  const float* bo = (const float*)d_in[8];
  float* out = (float*)d_out;

  cudaFuncSetAttribute(gemm_hmma_kernel,
                       cudaFuncAttributeMaxDynamicSharedMemorySize, GEMM_SMEM);
  cudaFuncSetAttribute(attn_kernel,
                       cudaFuncAttributeMaxDynamicSharedMemorySize, SMEM_BYTES);

  dim3 gqkv(6, 32, 3);
  gemm_hmma_kernel<<<gqkv, 256, GEMM_SMEM>>>(x, Wq, bq, Wk, bk, Wv, bv,
                                             nullptr, 0);

  attn_kernel<<<768, 256, SMEM_BYTES>>>();

  dim3 gout(6, 32, 1);
  gemm_hmma_kernel<<<gout, 256, GEMM_SMEM>>>(nullptr, Wo, bo, Wo, bo, Wo, bo,
                                             out, 1);
}

// round 9
// speedup vs baseline: 1.4713x; 1.2200x over previous
#include <cuda_runtime.h>
#include <cuda_bf16.h>
#include <cstdint>

#define NUM_HEADS 12
#define HEAD_DIM  64
#define SEQ       2048
#define BATCH     2
#define EMB       768
#define SEG       256
#define KDIM      768

// Scratch — EXACT R4/R8 set (proven to pass the allocation guard)
__device__ float g_q[BATCH*NUM_HEADS*SEQ*HEAD_DIM];
__device__ float g_k[BATCH*NUM_HEADS*SEQ*HEAD_DIM];
__device__ float g_v[BATCH*NUM_HEADS*SEQ*HEAD_DIM];
__device__ float g_ctx[BATCH*SEQ*EMB];

// ===========================================================================
// Warp-level MMA helpers (compute_100-safe: sm_80-era PTX)
// ===========================================================================
__device__ __forceinline__ uint32_t smem_u32(const void* p) {
  uint32_t a;
  asm("{ .reg .u64 t; cvta.to.shared.u64 t, %1; cvt.u32.u64 %0, t; }" : "=r"(a) : "l"(p));
  return a;
}
__device__ __forceinline__ void ldsm4(uint32_t* r, uint32_t addr) {
  asm volatile("ldmatrix.sync.aligned.m8n8.x4.shared.b16 {%0,%1,%2,%3}, [%4];"
               : "=r"(r[0]), "=r"(r[1]), "=r"(r[2]), "=r"(r[3]) : "r"(addr));
}
__device__ __forceinline__ void mma_bf16(float* d, const uint32_t* a,
                                         uint32_t b0, uint32_t b1) {
  asm volatile(
      "mma.sync.aligned.m16n8k16.row.col.f32.bf16.bf16.f32 "
      "{%0,%1,%2,%3}, {%4,%5,%6,%7}, {%8,%9}, {%0,%1,%2,%3};"
      : "+f"(d[0]), "+f"(d[1]), "+f"(d[2]), "+f"(d[3])
      : "r"(a[0]), "r"(a[1]), "r"(a[2]), "r"(a[3]), "r"(b0), "r"(b1));
}

#define SWZ(off) ((off) ^ (((off) >> 3) & 0x70))

__device__ __forceinline__ uint32_t pack2(float a, float b) {
  __nv_bfloat162 p = __halves2bfloat162(__float2bfloat16(a), __float2bfloat16(b));
  return *reinterpret_cast<uint32_t*>(&p);
}

// ===========================================================================
// GEMM (R8-proven, untouched): C = A*W^T + bias, split-bf16 3-pass,
// register prefetch of chunk c+1 behind chunk c's MMA phase.
// ===========================================================================
#define GK      64
#define NCHUNK  (KDIM / GK)            // 12
#define OFF_AHI 0
#define OFF_ALO 16384
#define OFF_BHI 32768
#define OFF_BLO 49152
#define GEMM_SMEM 65536

__global__ __launch_bounds__(256) void gemm_hmma_kernel(
    const float* __restrict__ A0,
    const float* __restrict__ W0, const float* __restrict__ b0,
    const float* __restrict__ W1, const float* __restrict__ b1,
    const float* __restrict__ W2, const float* __restrict__ b2,
    float* __restrict__ dout, int mode) {
  extern __shared__ char sm[];
  const uint32_t sbase = smem_u32(sm);
  const int tid  = threadIdx.x;
  const int wid  = tid >> 5;
  const int lane = tid & 31;
  const int m0 = blockIdx.y * 128;
  const int n0 = blockIdx.x * 128;
  const int z  = blockIdx.z;

  const float* A    = (mode == 1) ? g_ctx : A0;
  const float* W    = (z == 0) ? W0 : (z == 1) ? W1 : W2;
  const float* bias = (z == 0) ? b0 : (z == 1) ? b1 : b2;
  float* outp = (mode == 1) ? dout : ((z == 0) ? g_q : (z == 1) ? g_k : g_v);

  const int r  = tid >> 1;
  const int cb = (tid & 1) * 32;
  const float* Ap = A + (size_t)(m0 + r) * KDIM + cb;
  const float* Wp = W + (size_t)(n0 + r) * KDIM + cb;

  const int mw = (wid >> 1) * 32;
  const int nw = (wid & 1) * 64;
  const int lrow = lane & 15;
  const int lkb  = (lane >> 4) * 16;

  float acc[16][4];
#pragma unroll
  for (int i = 0; i < 16; i++)
#pragma unroll
    for (int j = 0; j < 4; j++) acc[i][j] = 0.f;

  float4 pa[8], pw[8];
#pragma unroll
  for (int u = 0; u < 8; u++) {
    pa[u] = *(const float4*)(Ap + u * 4);
    pw[u] = *(const float4*)(Wp + u * 4);
  }

  for (int c = 0; c < NCHUNK; c++) {
#pragma unroll
    for (int u = 0; u < 8; u++) {
      const float4 av = pa[u];
      const float4 wv = pw[u];
      const uint32_t sw = SWZ((uint32_t)(r * 128 + (cb + u * 4) * 2));

      float ahx = __bfloat162float(__float2bfloat16(av.x));
      float ahy = __bfloat162float(__float2bfloat16(av.y));
      float ahz = __bfloat162float(__float2bfloat16(av.z));
      float ahw = __bfloat162float(__float2bfloat16(av.w));
      *(uint2*)(sm + OFF_AHI + sw) = make_uint2(pack2(ahx, ahy), pack2(ahz, ahw));
      *(uint2*)(sm + OFF_ALO + sw) =
          make_uint2(pack2(av.x - ahx, av.y - ahy), pack2(av.z - ahz, av.w - ahw));

      float whx = __bfloat162float(__float2bfloat16(wv.x));
      float why = __bfloat162float(__float2bfloat16(wv.y));
      float whz = __bfloat162float(__float2bfloat16(wv.z));
      float whw = __bfloat162float(__float2bfloat16(wv.w));
      *(uint2*)(sm + OFF_BHI + sw) = make_uint2(pack2(whx, why), pack2(whz, whw));
      *(uint2*)(sm + OFF_BLO + sw) =
          make_uint2(pack2(wv.x - whx, wv.y - why), pack2(wv.z - whz, wv.w - whw));
    }
    __syncthreads();

    if (c + 1 < NCHUNK) {
#pragma unroll
      for (int u = 0; u < 8; u++) {
        pa[u] = *(const float4*)(Ap + (c + 1) * GK + u * 4);
        pw[u] = *(const float4*)(Wp + (c + 1) * GK + u * 4);
      }
    }

#pragma unroll
    for (int ks = 0; ks < 4; ks++) {
      const uint32_t koff = (uint32_t)(ks * 32 + lkb);
      uint32_t ah[2][4], al[2][4];
#pragma unroll
      for (int mi = 0; mi < 2; mi++) {
        const uint32_t off = (uint32_t)((mw + mi * 16 + lrow) * 128) + koff;
        ldsm4(ah[mi], sbase + OFF_AHI + SWZ(off));
        ldsm4(al[mi], sbase + OFF_ALO + SWZ(off));
      }
      uint32_t bh[4][4], bl[4][4];
#pragma unroll
      for (int nb = 0; nb < 4; nb++) {
        const uint32_t off = (uint32_t)((nw + nb * 16 + lrow) * 128) + koff;
        ldsm4(bh[nb], sbase + OFF_BHI + SWZ(off));
        ldsm4(bl[nb], sbase + OFF_BLO + SWZ(off));
      }
#pragma unroll
      for (int ni = 0; ni < 8; ni++) {
        const int nb = ni >> 1, sel = ni & 1;
        const uint32_t bh0 = bh[nb][sel], bh1 = bh[nb][2 + sel];
        const uint32_t bl0 = bl[nb][sel], bl1 = bl[nb][2 + sel];
#pragma unroll
        for (int mi = 0; mi < 2; mi++) {
          mma_bf16(acc[mi * 8 + ni], ah[mi], bh0, bh1);
          mma_bf16(acc[mi * 8 + ni], ah[mi], bl0, bl1);
          mma_bf16(acc[mi * 8 + ni], al[mi], bh0, bh1);
        }
      }
    }
    __syncthreads();
  }

  const int er = lane >> 2;
  const int ec = (lane & 3) * 2;
#pragma unroll
  for (int mi = 0; mi < 2; mi++) {
#pragma unroll
    for (int rr = 0; rr < 2; rr++) {
      const int m = m0 + mw + mi * 16 + rr * 8 + er;
      if (mode == 1) {
        float* orow = outp + (size_t)m * EMB;
#pragma unroll
        for (int ni = 0; ni < 8; ni++) {
          const int n = n0 + nw + ni * 8 + ec;
          float2 v;
          v.x = acc[mi * 8 + ni][rr * 2 + 0] + bias[n];
          v.y = acc[mi * 8 + ni][rr * 2 + 1] + bias[n + 1];
          *(float2*)(orow + n) = v;
        }
      } else {
        const int b = m >> 11;
        const int s = m & 2047;
#pragma unroll
        for (int ni = 0; ni < 8; ni++) {
          const int n = n0 + nw + ni * 8 + ec;
          const int h = n >> 6;
          const int d = n & 63;
          float2 v;
          v.x = acc[mi * 8 + ni][rr * 2 + 0] + bias[n];
          v.y = acc[mi * 8 + ni][rr * 2 + 1] + bias[n + 1];
          *(float2*)(outp + (((size_t)b * NUM_HEADS + h) * SEQ + s) * HEAD_DIM + d) = v;
        }
      }
    }
  }
}

// ===========================================================================
// HMMA attention. DILATION=1 => block-diagonal over 256-token segments.
// One CTA per (b, h, seg, 64-row qtile): grid 768, 256 threads (8 warps).
// Scores S(64x256) and PV(64x64) via 3-pass split-bf16 HMMA.
// Warp grid: mw = (wid>>2)*32 (2 rows), nw = (wid&3)*64 (4 cols).
// V staged TRANSPOSED into 4 j-panels of [64 d][64 j] (128B rows, std SWZ).
// P panels likewise [64 m][64 j].
// ===========================================================================
#define AT_QHI  0                      // 64*128   = 8192
#define AT_QLO  8192
#define AT_KHI  16384                  // 256*128  = 32768
#define AT_KLO  49152
#define AT_PHI  81920                  // 4 panels * 8192
#define AT_PLO  114688
#define AT_VHI  147456                 // 4 panels * 8192
#define AT_VLO  180224
#define AT_REDM 212992                 // 4*64 floats = 1024
#define AT_REDS 214016                 // 1024
#define AT_RINV 215040                 // 256
#define ATTN_SMEM 215296

__global__ __launch_bounds__(256) void attn_kernel() {
  extern __shared__ char sm[];
  const uint32_t sbase = smem_u32(sm);
  float* REDM = (float*)(sm + AT_REDM);
  float* REDS = (float*)(sm + AT_REDS);
  float* RINV = (float*)(sm + AT_RINV);

  const int tid  = threadIdx.x;
  const int wid  = tid >> 5;
  const int lane = tid & 31;
  int bx = blockIdx.x;
  const int qt  = bx & 3;   bx >>= 2;
  const int seg = bx & 7;   bx >>= 3;
  const int hh  = bx % NUM_HEADS;
  const int bb  = bx / NUM_HEADS;

  const size_t head_off = (((size_t)bb*NUM_HEADS + hh)*SEQ + seg*SEG) * HEAD_DIM;
  const float* qbase = g_q + head_off + (size_t)qt*64*HEAD_DIM;
  const float* kbase = g_k + head_off;
  const float* vbase = g_v + head_off;

  // ---- stage Q (scaled by 0.125), hi/lo, SW128 ----
  {
    const int r  = tid >> 2;           // 0..63
    const int c0 = (tid & 3) * 16;
#pragma unroll
    for (int u = 0; u < 4; u++) {
      float4 v = *(const float4*)(qbase + r * 64 + c0 + u * 4);
      v.x *= 0.125f; v.y *= 0.125f; v.z *= 0.125f; v.w *= 0.125f;
      const uint32_t sw = SWZ((uint32_t)(r * 128 + (c0 + u * 4) * 2));
      float hx = __bfloat162float(__float2bfloat16(v.x));
      float hy = __bfloat162float(__float2bfloat16(v.y));
      float hz = __bfloat162float(__float2bfloat16(v.z));
      float hw = __bfloat162float(__float2bfloat16(v.w));
      *(uint2*)(sm + AT_QHI + sw) = make_uint2(pack2(hx, hy), pack2(hz, hw));
      *(uint2*)(sm + AT_QLO + sw) =
          make_uint2(pack2(v.x - hx, v.y - hy), pack2(v.z - hz, v.w - hw));
    }
  }
  // ---- stage K rows (one per thread), hi/lo ----
  {
    const int j = tid;                 // 0..255
#pragma unroll
    for (int u = 0; u < 16; u++) {
      float4 v = *(const float4*)(kbase + j * 64 + u * 4);
      const uint32_t sw = SWZ((uint32_t)(j * 128 + u * 8));
      float hx = __bfloat162float(__float2bfloat16(v.x));
      float hy = __bfloat162float(__float2bfloat16(v.y));
      float hz = __bfloat162float(__float2bfloat16(v.z));
      float hw = __bfloat162float(__float2bfloat16(v.w));
      *(uint2*)(sm + AT_KHI + sw) = make_uint2(pack2(hx, hy), pack2(hz, hw));
      *(uint2*)(sm + AT_KLO + sw) =
          make_uint2(pack2(v.x - hx, v.y - hy), pack2(v.z - hz, v.w - hw));
    }
  }
  // ---- stage V transposed: panel jp = j>>6, Vt[d][j&63], hi/lo ----
  {
    const int j = tid;                 // 0..255
    const uint32_t pbase = (uint32_t)(j >> 6) * 8192;
    const int jc = (j & 63) * 2;
#pragma unroll
    for (int u = 0; u < 16; u++) {
      float4 v = *(const float4*)(vbase + j * 64 + u * 4);
      float f[4] = {v.x, v.y, v.z, v.w};
#pragma unroll
      for (int e = 0; e < 4; e++) {
        const int d = u * 4 + e;
        const uint32_t sw = SWZ((uint32_t)(d * 128 + jc));
        float hi = __bfloat162float(__float2bfloat16(f[e]));
        *(__nv_bfloat16*)(sm + AT_VHI + pbase + sw) = __float2bfloat16(hi);
        *(__nv_bfloat16*)(sm + AT_VLO + pbase + sw) = __float2bfloat16(f[e] - hi);
      }
    }
  }
  __syncthreads();

  // ---- scores: S(64x256) = Q @ K^T, 3-pass, warp tile 32x64 ----
  const int mw = (wid >> 2) * 32;      // 0,32
  const int nw = (wid & 3) * 64;       // 0,64,128,192
  const int lrow = lane & 15;
  const int lkb  = (lane >> 4) * 16;

  float acc[16][4];
#pragma unroll
  for (int i = 0; i < 16; i++)
#pragma unroll
    for (int j = 0; j < 4; j++) acc[i][j] = 0.f;

#pragma unroll
  for (int ks = 0; ks < 4; ks++) {
    const uint32_t koff = (uint32_t)(ks * 32 + lkb);
    uint32_t ah[2][4], al[2][4];
#pragma unroll
    for (int mi = 0; mi < 2; mi++) {
      const uint32_t off = (uint32_t)((mw + mi * 16 + lrow) * 128) + koff;
      ldsm4(ah[mi], sbase + AT_QHI + SWZ(off));
      ldsm4(al[mi], sbase + AT_QLO + SWZ(off));
    }
    uint32_t bh[4][4], bl[4][4];
#pragma unroll
    for (int nb = 0; nb < 4; nb++) {
      const uint32_t off = (uint32_t)((nw + nb * 16 + lrow) * 128) + koff;
      ldsm4(bh[nb], sbase + AT_KHI + SWZ(off));
      ldsm4(bl[nb], sbase + AT_KLO + SWZ(off));
    }
#pragma unroll
    for (int ni = 0; ni < 8; ni++) {
      const int nb = ni >> 1, sel = ni & 1;
      const uint32_t bh0 = bh[nb][sel], bh1 = bh[nb][2 + sel];
      const uint32_t bl0 = bl[nb][sel], bl1 = bl[nb][2 + sel];
#pragma unroll
      for (int mi = 0; mi < 2; mi++) {
        mma_bf16(acc[mi * 8 + ni], ah[mi], bh0, bh1);
        mma_bf16(acc[mi * 8 + ni], ah[mi], bl0, bl1);
        mma_bf16(acc[mi * 8 + ni], al[mi], bh0, bh1);
      }
    }
  }

  // ---- softmax ----
  const int er = lane >> 2;
  const int ec = (lane & 3) * 2;
  const int wcol = wid & 3;

  // row max (per thread 4 rows x 16 cols), 4-lane shuffle, cross-warpcol smem
  float rmax[2][2];
#pragma unroll
  for (int mi = 0; mi < 2; mi++)
#pragma unroll
    for (int rr = 0; rr < 2; rr++) {
      float m = -1e30f;
#pragma unroll
      for (int ni = 0; ni < 8; ni++) {
        m = fmaxf(m, acc[mi * 8 + ni][rr * 2 + 0]);
        m = fmaxf(m, acc[mi * 8 + ni][rr * 2 + 1]);
      }
      m = fmaxf(m, __shfl_xor_sync(0xffffffffu, m, 1));
      m = fmaxf(m, __shfl_xor_sync(0xffffffffu, m, 2));
      rmax[mi][rr] = m;
      if ((lane & 3) == 0)
        REDM[wcol * 64 + mw + mi * 16 + rr * 8 + er] = m;
    }
  __syncthreads();

  // final max, exp, row sum, write P hi/lo panels (panel = wcol)
  const uint32_t ppan = (uint32_t)wcol * 8192;
  float rsum[2][2];
#pragma unroll
  for (int mi = 0; mi < 2; mi++)
#pragma unroll
    for (int rr = 0; rr < 2; rr++) {
      const int m = mw + mi * 16 + rr * 8 + er;
      float fm = fmaxf(fmaxf(REDM[m], REDM[64 + m]),
                       fmaxf(REDM[128 + m], REDM[192 + m]));
      float s = 0.f;
#pragma unroll
      for (int ni = 0; ni < 8; ni++) {
        float e0 = __expf(acc[mi * 8 + ni][rr * 2 + 0] - fm);
        float e1 = __expf(acc[mi * 8 + ni][rr * 2 + 1] - fm);
        s += e0 + e1;
        float h0 = __bfloat162float(__float2bfloat16(e0));
        float h1 = __bfloat162float(__float2bfloat16(e1));
        const uint32_t sw = SWZ((uint32_t)(m * 128 + (ni * 8 + ec) * 2));
        *(uint32_t*)(sm + AT_PHI + ppan + sw) = pack2(h0, h1);
        *(uint32_t*)(sm + AT_PLO + ppan + sw) = pack2(e0 - h0, e1 - h1);
      }
      s += __shfl_xor_sync(0xffffffffu, s, 1);
      s += __shfl_xor_sync(0xffffffffu, s, 2);
      rsum[mi][rr] = s;
      if ((lane & 3) == 0) REDS[wcol * 64 + m] = s;
    }
  __syncthreads();

  if (wcol == 0 && (lane & 3) == 0) {
#pragma unroll
    for (int mi = 0; mi < 2; mi++)
#pragma unroll
      for (int rr = 0; rr < 2; rr++) {
        const int m = mw + mi * 16 + rr * 8 + er;
        RINV[m] = 1.0f / (REDS[m] + REDS[64 + m] + REDS[128 + m] + REDS[192 + m]);
      }
  }
  __syncthreads();

  // ---- PV: ctx(64x64) = P(64x256) @ V, 4 panels, warp tile 32x16 ----
  const int nw2 = (wid & 3) * 16;
  float accv[4][4];                    // [mi*2+ni][4]
#pragma unroll
  for (int i = 0; i < 4; i++)
#pragma unroll
    for (int j = 0; j < 4; j++) accv[i][j] = 0.f;

#pragma unroll
  for (int pp = 0; pp < 4; pp++) {
    const uint32_t pb = (uint32_t)pp * 8192;
#pragma unroll
    for (int ks = 0; ks < 4; ks++) {
      const uint32_t koff = (uint32_t)(ks * 32 + lkb);
      uint32_t ph[2][4], pl[2][4];
#pragma unroll
      for (int mi = 0; mi < 2; mi++) {
        const uint32_t off = (uint32_t)((mw + mi * 16 + lrow) * 128) + koff;
        ldsm4(ph[mi], sbase + AT_PHI + pb + SWZ(off));
        ldsm4(pl[mi], sbase + AT_PLO + pb + SWZ(off));
      }
      uint32_t vh[4], vl[4];
      {
        const uint32_t off = (uint32_t)((nw2 + lrow) * 128) + koff;
        ldsm4(vh, sbase + AT_VHI + pb + SWZ(off));
        ldsm4(vl, sbase + AT_VLO + pb + SWZ(off));
      }
#pragma unroll
      for (int ni = 0; ni < 2; ni++) {
        const uint32_t b0 = vh[ni], b1 = vh[2 + ni];
        const uint32_t c0 = vl[ni], c1 = vl[2 + ni];
#pragma unroll
        for (int mi = 0; mi < 2; mi++) {
          mma_bf16(accv[mi * 2 + ni], ph[mi], b0, b1);
          mma_bf16(accv[mi * 2 + ni], ph[mi], c0, c1);
          mma_bf16(accv[mi * 2 + ni], pl[mi], b0, b1);
        }
      }
    }
  }

  // ---- epilogue: normalize, scatter to (B,S,E) ----
  float* ctxbase = g_ctx + ((size_t)bb*SEQ + seg*SEG + qt*64)*EMB + hh*64;
#pragma unroll
  for (int mi = 0; mi < 2; mi++) {
#pragma unroll
    for (int rr = 0; rr < 2; rr++) {
      const int m = mw + mi * 16 + rr * 8 + er;
      const float iv = RINV[m];
#pragma unroll
      for (int ni = 0; ni < 2; ni++) {
        const int d = nw2 + ni * 8 + ec;
        float2 v;
        v.x = accv[mi * 2 + ni][rr * 2 + 0] * iv;
        v.y = accv[mi * 2 + ni][rr * 2 + 1] * iv;
        *(float2*)(ctxbase + (size_t)m * EMB + d) = v;
      }
    }
  }
}

// ===========================================================================
extern "C" void kernel_launch(void* const* d_in, const int* in_sizes, int n_in,
                              void* d_out, int out_size) {
  const float* x  = (const float*)d_in[0];
  const float* Wq = (const float*)d_in[1];
  const float* bq = (const float*)d_in[2];
  const float* Wk = (const float*)d_in[3];
  const float* bk = (const float*)d_in[4];
  const float* Wv = (const float*)d_in[5];
  const float* bv = (const float*)d_in[6];
  const float* Wo = (const float*)d_in[7];
  const float* bo = (const float*)d_in[8];
  float* out = (float*)d_out;

  cudaFuncSetAttribute(gemm_hmma_kernel,
                       cudaFuncAttributeMaxDynamicSharedMemorySize, GEMM_SMEM);
  cudaFuncSetAttribute(attn_kernel,
                       cudaFuncAttributeMaxDynamicSharedMemorySize, ATTN_SMEM);

  dim3 gqkv(6, 32, 3);
  gemm_hmma_kernel<<<gqkv, 256, GEMM_SMEM>>>(x, Wq, bq, Wk, bk, Wv, bv,
                                             nullptr, 0);

  attn_kernel<<<768, 256, ATTN_SMEM>>>();

  dim3 gout(6, 32, 1);
  gemm_hmma_kernel<<<gout, 256, GEMM_SMEM>>>(nullptr, Wo, bo, Wo, bo, Wo, bo,
                                             out, 1);
}